// round 10
// baseline (speedup 1.0000x reference)
#include <cuda_runtime.h>
#include <cuda_bf16.h>
#include <cstdint>

// Problem constants (fixed by the reference setup_inputs)
#define N_USERS_C 200000
#define NN_C      300000          // N_USERS + N_ITEMS
#define D_C       64
#define NEDGES_C  1200000
#define EB        4688            // ceil(NEDGES_C / 256)
#define CAP       24              // per-row bin capacity (max observed deg ~18)

// Scratch (device globals; zero-init at load).
// g_counts: bucket fills (atomic cursors) -> fused reads degree and zeroes.
// g_spill_n: starts 0; bucket fills; fused reads, last-finishing block zeroes.
__device__ int  g_counts[NN_C];
__device__ int2 g_edges [(size_t)NN_C * CAP];   // (col, bitcast(val)) binned by row
__device__ int  g_spill_n;
__device__ int4 g_spill [NEDGES_C];             // (row, col, bitcast(val), 0) overflow
__device__ int  g_general;                      // 1 if filt != eye(64)
__device__ unsigned int g_done;                 // fused completion ticket

// ---------------------------------------------------------------------------
// K0: bucket edges into fixed-capacity row bins; block 0 also checks filt.
//     Overflow (never on this data) goes to the spill list — still correct.
// ---------------------------------------------------------------------------
__global__ void __launch_bounds__(256)
k_bucket(const int* __restrict__ adj_rows,
         const int* __restrict__ adj_cols,
         const float* __restrict__ adj_vals,
         const float* __restrict__ filt) {
    if (blockIdx.x == 0) {
        __shared__ int s_bad;
        if (threadIdx.x == 0) s_bad = 0;
        __syncthreads();
        int bad = 0;
        for (int i = threadIdx.x; i < D_C * D_C; i += 256) {
            float expect = ((i >> 6) == (i & 63)) ? 1.0f : 0.0f;
            if (filt[i] != expect) bad = 1;
        }
        if (bad) atomicOr(&s_bad, 1);
        __syncthreads();
        if (threadIdx.x == 0) g_general = s_bad;
    }

    int e = blockIdx.x * 256 + threadIdx.x;
    if (e >= NEDGES_C) return;
    int r   = adj_rows[e];
    int c   = adj_cols[e];
    int v   = __float_as_int(adj_vals[e]);
    int pos = atomicAdd(&g_counts[r], 1);
    if (pos < CAP) {
        g_edges[(size_t)r * CAP + pos] = make_int2(c, v);
    } else {
        int s = atomicAdd(&g_spill_n, 1);
        g_spill[s] = make_int4(r, c, v, 0);
    }
}

// ---------------------------------------------------------------------------
// K1: fused segment-sum + finalize. EIGHT rows per warp (4 lanes per row,
//     lane owns 4 interleaved float4s) -> 8 independent gather chains/warp,
//     up to ~16 outstanding loads; trip count = max(deg of 8 rows).
//     Block = 128 threads (4 warps, 32 rows); grid = 9375 (exact).
// ---------------------------------------------------------------------------
__global__ void __launch_bounds__(128)
k_fused(const float* __restrict__ user_emb,
        const float* __restrict__ item_emb,
        const float* __restrict__ filt,
        float* __restrict__ out) {
    __shared__ float s_filt[D_C * D_C];     // general path only
    __shared__ float s_t[4][8][D_C];        // general path only

    const int gen = g_general;              // uniform
    if (gen) {
        for (int i = threadIdx.x; i < D_C * D_C; i += blockDim.x)
            s_filt[i] = filt[i];
        __syncthreads();
    }

    const int w    = threadIdx.x >> 5;      // warp in block (0..3)
    const int lane = threadIdx.x & 31;
    const int g    = lane >> 2;             // row-group within warp (0..7)
    const int sl   = lane & 3;              // sublane within group (0..3)
    const int r    = blockIdx.x * 32 + w * 8 + g;   // 9375*32 == 300000

    // own-row emb (four float4s), issued before the edge loop
    const float4* esrc = (r < N_USERS_C)
        ? (const float4*)(user_emb + (size_t)r * D_C)
        : (const float4*)(item_emb + (size_t)(r - N_USERS_C) * D_C);
    float4 e0 = __ldg(&esrc[sl]);
    float4 e1 = __ldg(&esrc[sl + 4]);
    float4 e2 = __ldg(&esrc[sl + 8]);
    float4 e3 = __ldg(&esrc[sl + 12]);

    const int deg  = g_counts[r];
    const int ncap = min(deg, CAP);
    if (sl == 0) g_counts[r] = 0;           // reset cursors for next replay

    // warp-uniform trip count = max ncap over the 8 groups
    int maxdeg = ncap;
    #pragma unroll
    for (int d = 16; d >= 1; d >>= 1)
        maxdeg = max(maxdeg, __shfl_xor_sync(0xffffffffu, maxdeg, d));

    const int2* row_edges = &g_edges[(size_t)r * CAP];
    float4 a0 = make_float4(0.f, 0.f, 0.f, 0.f);
    float4 a1 = make_float4(0.f, 0.f, 0.f, 0.f);
    float4 a2 = make_float4(0.f, 0.f, 0.f, 0.f);
    float4 a3 = make_float4(0.f, 0.f, 0.f, 0.f);

    for (int i = 0; i < maxdeg; i++) {
        if (i < ncap) {
            int2 eg = __ldg(&row_edges[i]);     // broadcast in 4-lane group
            float val = __int_as_float(eg.y);
            const float4* src = (eg.x < N_USERS_C)
                ? (const float4*)(user_emb + (size_t)eg.x * D_C)
                : (const float4*)(item_emb + (size_t)(eg.x - N_USERS_C) * D_C);
            float4 v0 = __ldg(&src[sl]);        // 64B per group per load
            float4 v1 = __ldg(&src[sl + 4]);
            float4 v2 = __ldg(&src[sl + 8]);
            float4 v3 = __ldg(&src[sl + 12]);
            a0.x = fmaf(val, v0.x, a0.x); a0.y = fmaf(val, v0.y, a0.y);
            a0.z = fmaf(val, v0.z, a0.z); a0.w = fmaf(val, v0.w, a0.w);
            a1.x = fmaf(val, v1.x, a1.x); a1.y = fmaf(val, v1.y, a1.y);
            a1.z = fmaf(val, v1.z, a1.z); a1.w = fmaf(val, v1.w, a1.w);
            a2.x = fmaf(val, v2.x, a2.x); a2.y = fmaf(val, v2.y, a2.y);
            a2.z = fmaf(val, v2.z, a2.z); a2.w = fmaf(val, v2.w, a2.w);
            a3.x = fmaf(val, v3.x, a3.x); a3.y = fmaf(val, v3.y, a3.y);
            a3.z = fmaf(val, v3.z, a3.z); a3.w = fmaf(val, v3.w, a3.w);
        }
    }

    // Overflow path (never taken on this data; uniform guard, zero cost)
    const int spill_n = g_spill_n;
    if (spill_n > 0 && deg > CAP) {
        for (int i = 0; i < spill_n; i++) {
            int4 sp = g_spill[i];
            if (sp.x == r) {
                float val = __int_as_float(sp.z);
                const float4* src = (sp.y < N_USERS_C)
                    ? (const float4*)(user_emb + (size_t)sp.y * D_C)
                    : (const float4*)(item_emb + (size_t)(sp.y - N_USERS_C) * D_C);
                float4 v0 = __ldg(&src[sl]);
                float4 v1 = __ldg(&src[sl + 4]);
                float4 v2 = __ldg(&src[sl + 8]);
                float4 v3 = __ldg(&src[sl + 12]);
                a0.x = fmaf(val, v0.x, a0.x); a0.y = fmaf(val, v0.y, a0.y);
                a0.z = fmaf(val, v0.z, a0.z); a0.w = fmaf(val, v0.w, a0.w);
                a1.x = fmaf(val, v1.x, a1.x); a1.y = fmaf(val, v1.y, a1.y);
                a1.z = fmaf(val, v1.z, a1.z); a1.w = fmaf(val, v1.w, a1.w);
                a2.x = fmaf(val, v2.x, a2.x); a2.y = fmaf(val, v2.y, a2.y);
                a2.z = fmaf(val, v2.z, a2.z); a2.w = fmaf(val, v2.w, a2.w);
                a3.x = fmaf(val, v3.x, a3.x); a3.y = fmaf(val, v3.y, a3.y);
                a3.z = fmaf(val, v3.z, a3.z); a3.w = fmaf(val, v3.w, a3.w);
            }
        }
    }

    float4 t0 = make_float4(2.f*e0.x - a0.x, 2.f*e0.y - a0.y, 2.f*e0.z - a0.z, 2.f*e0.w - a0.w);
    float4 t1 = make_float4(2.f*e1.x - a1.x, 2.f*e1.y - a1.y, 2.f*e1.z - a1.z, 2.f*e1.w - a1.w);
    float4 t2 = make_float4(2.f*e2.x - a2.x, 2.f*e2.y - a2.y, 2.f*e2.z - a2.z, 2.f*e2.w - a2.w);
    float4 t3 = make_float4(2.f*e3.x - a3.x, 2.f*e3.y - a3.y, 2.f*e3.z - a3.z, 2.f*e3.w - a3.w);

    float4* orow = (float4*)(out + (size_t)r * 128);
    orow[sl]      = e0;                     // [0:64) = emb
    orow[sl + 4]  = e1;
    orow[sl + 8]  = e2;
    orow[sl + 12] = e3;

    if (!gen) {
        #define SIG4(t) make_float4(1.f/(1.f+__expf(-(t).x)), 1.f/(1.f+__expf(-(t).y)), \
                                    1.f/(1.f+__expf(-(t).z)), 1.f/(1.f+__expf(-(t).w)))
        orow[16 + sl]      = SIG4(t0);      // [64:128) = sigmoid(t)
        orow[16 + sl + 4]  = SIG4(t1);
        orow[16 + sl + 8]  = SIG4(t2);
        orow[16 + sl + 12] = SIG4(t3);
        #undef SIG4
    } else {
        float4* st = (float4*)s_t[w][g];
        st[sl]      = t0;
        st[sl + 4]  = t1;
        st[sl + 8]  = t2;
        st[sl + 12] = t3;
        __syncwarp();
        float a[16];
        #pragma unroll
        for (int jj = 0; jj < 16; jj++) a[jj] = 0.f;
        #pragma unroll 4
        for (int k = 0; k < D_C; k++) {
            float tk = s_t[w][g][k];
            #pragma unroll
            for (int jj = 0; jj < 16; jj++)
                a[jj] = fmaf(tk, s_filt[k * D_C + sl + 4 * jj], a[jj]);
        }
        #pragma unroll
        for (int jj = 0; jj < 16; jj++)
            out[(size_t)r * 128 + 64 + sl + 4 * jj] = 1.f / (1.f + __expf(-a[jj]));
    }

    // Last-finishing block resets g_spill_n (all blocks have consumed the
    // spill list before incrementing the ticket) and the ticket itself.
    __syncthreads();
    if (threadIdx.x == 0) {
        __threadfence();
        unsigned int t = atomicAdd(&g_done, 1u);
        if (t == gridDim.x - 1) {
            g_spill_n = 0;
            g_done = 0;
        }
    }
}

// ---------------------------------------------------------------------------
// Launch. Inputs (metadata order):
//   0: adj_rows (i32 1.2M)  1: adj_cols (i32 1.2M)  2: adj_vals (f32 1.2M)
//   3: user_emb (f32 200000*64)  4: item_emb (f32 100000*64)  5: filt (64*64)
// Output: 300000 rows of [emb | h] (f32, 128 wide), users then items.
// ---------------------------------------------------------------------------
extern "C" void kernel_launch(void* const* d_in, const int* in_sizes, int n_in,
                              void* d_out, int out_size) {
    const int*   adj_rows = (const int*)  d_in[0];
    const int*   adj_cols = (const int*)  d_in[1];
    const float* adj_vals = (const float*)d_in[2];
    const float* user_emb = (const float*)d_in[3];
    const float* item_emb = (const float*)d_in[4];
    const float* filt     = (const float*)d_in[5];
    float* out = (float*)d_out;

    k_bucket<<<EB, 256>>>(adj_rows, adj_cols, adj_vals, filt);
    k_fused <<<NN_C / 32, 128>>>(user_emb, item_emb, filt, out);
}

// round 11
// speedup vs baseline: 1.2469x; 1.2469x over previous
#include <cuda_runtime.h>
#include <cuda_bf16.h>
#include <cstdint>

// Problem constants (fixed by the reference setup_inputs)
#define N_USERS_C 200000
#define NN_C      300000          // N_USERS + N_ITEMS
#define D_C       64
#define NEDGES_C  1200000
#define EB        4688            // ceil(NEDGES_C / 256)
#define CAP       24              // per-row bin capacity (max observed deg ~18)

// Scratch (device globals; zero-init at load).
// g_counts: bucket fills (atomic cursors) -> fused reads degree and zeroes.
// g_spill_n: starts 0; bucket fills; fused reads; last fused block zeroes.
__device__ int  g_counts[NN_C];
__device__ int2 g_edges [(size_t)NN_C * CAP];   // (col, bitcast(val)) binned by row
__device__ int  g_spill_n;
__device__ int4 g_spill [NEDGES_C];             // (row, col, bitcast(val), 0) overflow
__device__ int  g_general;                      // 1 if filt != eye(64)
__device__ unsigned int g_done;                 // fused completion ticket

// ---------------------------------------------------------------------------
// K0: bucket edges into fixed-capacity row bins; block 0 also checks filt.
//     Overflow (never on this data) goes to the spill list — still correct.
// ---------------------------------------------------------------------------
__global__ void __launch_bounds__(256)
k_bucket(const int* __restrict__ adj_rows,
         const int* __restrict__ adj_cols,
         const float* __restrict__ adj_vals,
         const float* __restrict__ filt) {
    if (blockIdx.x == 0) {
        __shared__ int s_bad;
        if (threadIdx.x == 0) s_bad = 0;
        __syncthreads();
        int bad = 0;
        for (int i = threadIdx.x; i < D_C * D_C; i += 256) {
            float expect = ((i >> 6) == (i & 63)) ? 1.0f : 0.0f;
            if (filt[i] != expect) bad = 1;
        }
        if (bad) atomicOr(&s_bad, 1);
        __syncthreads();
        if (threadIdx.x == 0) g_general = s_bad;
    }

    int e = blockIdx.x * 256 + threadIdx.x;
    if (e >= NEDGES_C) return;
    int r   = adj_rows[e];
    int c   = adj_cols[e];
    int v   = __float_as_int(adj_vals[e]);
    int pos = atomicAdd(&g_counts[r], 1);
    if (pos < CAP) {
        g_edges[(size_t)r * CAP + pos] = make_int2(c, v);
    } else {
        int s = atomicAdd(&g_spill_n, 1);
        g_spill[s] = make_int4(r, c, v, 0);
    }
}

// ---------------------------------------------------------------------------
// K1: fused segment-sum + finalize. FOUR rows per warp (8 lanes per row,
//     lane owns 2 float4s) — the best-measured geometry (R9) — now with
//     ZERO shared memory and a lean register file for high occupancy.
//     Fast path writes sigmoid(t); general path writes raw t (k_general
//     finishes it). Block = 256 (8 warps, 32 rows); grid = 9375 (exact).
// ---------------------------------------------------------------------------
__global__ void __launch_bounds__(256)
k_fused(const float* __restrict__ user_emb,
        const float* __restrict__ item_emb,
        float* __restrict__ out) {
    const int gen  = g_general;             // uniform
    const int w    = threadIdx.x >> 5;      // warp in block (0..7)
    const int lane = threadIdx.x & 31;
    const int g    = lane >> 3;             // row-group within warp (0..3)
    const int sl   = lane & 7;              // sublane within group (0..7)
    const int r    = blockIdx.x * 32 + w * 4 + g;   // 9375*32 == 300000

    // own-row emb (two float4s), issued before the edge loop
    const float4* esrc = (r < N_USERS_C)
        ? (const float4*)(user_emb + (size_t)r * D_C)
        : (const float4*)(item_emb + (size_t)(r - N_USERS_C) * D_C);
    float4 e0 = __ldg(&esrc[sl]);
    float4 e1 = __ldg(&esrc[sl + 8]);

    const int deg  = g_counts[r];
    const int ncap = min(deg, CAP);
    if (sl == 0) g_counts[r] = 0;           // reset cursors for next replay

    // warp-uniform trip count = max ncap over the 4 groups
    int maxdeg = ncap;
    #pragma unroll
    for (int d = 16; d >= 1; d >>= 1)
        maxdeg = max(maxdeg, __shfl_xor_sync(0xffffffffu, maxdeg, d));

    const int2* row_edges = &g_edges[(size_t)r * CAP];
    float4 a0 = make_float4(0.f, 0.f, 0.f, 0.f);
    float4 a1 = make_float4(0.f, 0.f, 0.f, 0.f);

    for (int i = 0; i < maxdeg; i++) {
        if (i < ncap) {
            int2 eg = __ldg(&row_edges[i]);         // broadcast in 8-lane group
            float val = __int_as_float(eg.y);
            const float4* src = (eg.x < N_USERS_C)
                ? (const float4*)(user_emb + (size_t)eg.x * D_C)
                : (const float4*)(item_emb + (size_t)(eg.x - N_USERS_C) * D_C);
            float4 v0 = __ldg(&src[sl]);            // 128B per group
            float4 v1 = __ldg(&src[sl + 8]);        // 128B per group
            a0.x = fmaf(val, v0.x, a0.x); a0.y = fmaf(val, v0.y, a0.y);
            a0.z = fmaf(val, v0.z, a0.z); a0.w = fmaf(val, v0.w, a0.w);
            a1.x = fmaf(val, v1.x, a1.x); a1.y = fmaf(val, v1.y, a1.y);
            a1.z = fmaf(val, v1.z, a1.z); a1.w = fmaf(val, v1.w, a1.w);
        }
    }

    // Overflow path (never taken on this data; uniform guard, zero cost)
    const int spill_n = g_spill_n;
    if (spill_n > 0 && deg > CAP) {
        for (int i = 0; i < spill_n; i++) {
            int4 sp = g_spill[i];
            if (sp.x == r) {
                float val = __int_as_float(sp.z);
                const float4* src = (sp.y < N_USERS_C)
                    ? (const float4*)(user_emb + (size_t)sp.y * D_C)
                    : (const float4*)(item_emb + (size_t)(sp.y - N_USERS_C) * D_C);
                float4 v0 = __ldg(&src[sl]);
                float4 v1 = __ldg(&src[sl + 8]);
                a0.x = fmaf(val, v0.x, a0.x); a0.y = fmaf(val, v0.y, a0.y);
                a0.z = fmaf(val, v0.z, a0.z); a0.w = fmaf(val, v0.w, a0.w);
                a1.x = fmaf(val, v1.x, a1.x); a1.y = fmaf(val, v1.y, a1.y);
                a1.z = fmaf(val, v1.z, a1.z); a1.w = fmaf(val, v1.w, a1.w);
            }
        }
    }

    float4 t0 = make_float4(2.f*e0.x - a0.x, 2.f*e0.y - a0.y,
                            2.f*e0.z - a0.z, 2.f*e0.w - a0.w);
    float4 t1 = make_float4(2.f*e1.x - a1.x, 2.f*e1.y - a1.y,
                            2.f*e1.z - a1.z, 2.f*e1.w - a1.w);

    float4* orow = (float4*)(out + (size_t)r * 128);
    orow[sl]     = e0;                      // [0:64) = emb
    orow[sl + 8] = e1;

    if (!gen) {
        float4 h0 = make_float4(1.f/(1.f+__expf(-t0.x)), 1.f/(1.f+__expf(-t0.y)),
                                1.f/(1.f+__expf(-t0.z)), 1.f/(1.f+__expf(-t0.w)));
        float4 h1 = make_float4(1.f/(1.f+__expf(-t1.x)), 1.f/(1.f+__expf(-t1.y)),
                                1.f/(1.f+__expf(-t1.z)), 1.f/(1.f+__expf(-t1.w)));
        orow[16 + sl]     = h0;             // [64:128) = sigmoid(t)
        orow[16 + sl + 8] = h1;
    } else {
        orow[16 + sl]     = t0;             // raw t; k_general finishes it
        orow[16 + sl + 8] = t1;
    }

    // Last-finishing block resets g_spill_n and the ticket.
    __syncthreads();
    if (threadIdx.x == 0) {
        __threadfence();
        unsigned int t = atomicAdd(&g_done, 1u);
        if (t == gridDim.x - 1) {
            g_spill_n = 0;
            g_done = 0;
        }
    }
}

// ---------------------------------------------------------------------------
// K2: general-filt epilogue. No-op when filt == eye (uniform early exit).
//     One warp per row: stage t, matmul with filt, sigmoid, write in place.
// ---------------------------------------------------------------------------
__global__ void __launch_bounds__(256)
k_general(const float* __restrict__ filt, float* __restrict__ out) {
    if (!g_general) return;                 // uniform, ~free when identity

    __shared__ float s_filt[D_C * D_C];
    __shared__ float s_t[8][D_C];
    for (int i = threadIdx.x; i < D_C * D_C; i += blockDim.x)
        s_filt[i] = filt[i];
    __syncthreads();

    const int w    = threadIdx.x >> 5;
    const int lane = threadIdx.x & 31;

    for (int r = blockIdx.x * 8 + w; r < NN_C; r += gridDim.x * 8) {
        float2* trow = (float2*)(out + (size_t)r * 128 + 64);
        float2 t = trow[lane];
        s_t[w][2 * lane]     = t.x;
        s_t[w][2 * lane + 1] = t.y;
        __syncwarp();
        float a0 = 0.f, a1 = 0.f;
        #pragma unroll 8
        for (int k = 0; k < D_C; k++) {
            float tk = s_t[w][k];
            a0 = fmaf(tk, s_filt[k * D_C + 2 * lane],     a0);
            a1 = fmaf(tk, s_filt[k * D_C + 2 * lane + 1], a1);
        }
        __syncwarp();
        trow[lane] = make_float2(1.f / (1.f + __expf(-a0)),
                                 1.f / (1.f + __expf(-a1)));
    }
}

// ---------------------------------------------------------------------------
// Launch. Inputs (metadata order):
//   0: adj_rows (i32 1.2M)  1: adj_cols (i32 1.2M)  2: adj_vals (f32 1.2M)
//   3: user_emb (f32 200000*64)  4: item_emb (f32 100000*64)  5: filt (64*64)
// Output: 300000 rows of [emb | h] (f32, 128 wide), users then items.
// ---------------------------------------------------------------------------
extern "C" void kernel_launch(void* const* d_in, const int* in_sizes, int n_in,
                              void* d_out, int out_size) {
    const int*   adj_rows = (const int*)  d_in[0];
    const int*   adj_cols = (const int*)  d_in[1];
    const float* adj_vals = (const float*)d_in[2];
    const float* user_emb = (const float*)d_in[3];
    const float* item_emb = (const float*)d_in[4];
    const float* filt     = (const float*)d_in[5];
    float* out = (float*)d_out;

    k_bucket <<<EB, 256>>>(adj_rows, adj_cols, adj_vals, filt);
    k_fused  <<<NN_C / 32, 256>>>(user_emb, item_emb, out);
    k_general<<<1184, 256>>>(filt, out);
}